// round 2
// baseline (speedup 1.0000x reference)
#include <cuda_runtime.h>
#include <cuda_bf16.h>
#include <cstdint>

// out[t, d] = code[weight[row, d]] * absmax[row],  row = tokens[t]
// tokens [8192], weight [50400,4096] int32 codes, absmax [50400], code [256].
// Output [8192,4096] fp32. HBM-bound: 134 MB read + 134 MB write.
//
// R1 -> R2: persistent grid (LUT staged once per CTA, no per-token CTA
// launch bubbles), streaming cache hints (__ldcs/__stcs), front-batched loads.

static constexpr int DIM = 4096;
static constexpr int THREADS = 256;
static constexpr int VECS = DIM / 4;            // 1024 int4 per row
static constexpr int VEC_PER_THREAD = VECS / THREADS;  // 4

__device__ __forceinline__ int4 ldcs_int4(const int4* p) {
    int4 v;
    asm volatile("ld.global.cs.v4.b32 {%0,%1,%2,%3}, [%4];"
                 : "=r"(v.x), "=r"(v.y), "=r"(v.z), "=r"(v.w) : "l"(p));
    return v;
}

__device__ __forceinline__ void stcs_float4(float4* p, float4 v) {
    asm volatile("st.global.cs.v4.f32 [%0], {%1,%2,%3,%4};"
                 :: "l"(p), "f"(v.x), "f"(v.y), "f"(v.z), "f"(v.w) : "memory");
}

__global__ __launch_bounds__(THREADS)
void bnb_embed_kernel(const int* __restrict__ tokens,
                      const int* __restrict__ weight,
                      const float* __restrict__ absmax,
                      const float* __restrict__ code,
                      float* __restrict__ out,
                      int n_tokens)
{
    __shared__ float s_code[256];
    const int tid = threadIdx.x;
    s_code[tid] = code[tid];   // stage 1 KB LUT once per (persistent) CTA
    __syncthreads();

    for (int t = blockIdx.x; t < n_tokens; t += gridDim.x) {
        const int row = __ldg(&tokens[t]);
        const float scale = __ldg(&absmax[row]);

        const int4* __restrict__ wrow =
            reinterpret_cast<const int4*>(weight + (long long)row * DIM);
        float4* __restrict__ orow =
            reinterpret_cast<float4*>(out + (long long)t * DIM);

        // Front-batch all loads: 4 outstanding 16B streaming loads per thread.
        int4 q[VEC_PER_THREAD];
#pragma unroll
        for (int i = 0; i < VEC_PER_THREAD; i++)
            q[i] = ldcs_int4(&wrow[tid + i * THREADS]);

#pragma unroll
        for (int i = 0; i < VEC_PER_THREAD; i++) {
            float4 v;
            v.x = s_code[q[i].x] * scale;
            v.y = s_code[q[i].y] * scale;
            v.z = s_code[q[i].z] * scale;
            v.w = s_code[q[i].w] * scale;
            stcs_float4(&orow[tid + i * THREADS], v);
        }
    }
}

extern "C" void kernel_launch(void* const* d_in, const int* in_sizes, int n_in,
                              void* d_out, int out_size)
{
    const int*   tokens = (const int*)d_in[0];
    const int*   weight = (const int*)d_in[1];
    const float* absmax = (const float*)d_in[2];
    const float* code   = (const float*)d_in[3];
    float*       out    = (float*)d_out;

    const int n_tokens = in_sizes[0];   // 8192
    // Persistent grid: 8 CTAs/SM x 148 SMs = 1184 (regs=32, 256 thr -> fits 2048 thr/SM)
    const int grid = 1184;
    bnb_embed_kernel<<<grid, THREADS>>>(tokens, weight, absmax, code, out, n_tokens);
}